// round 14
// baseline (speedup 1.0000x reference)
#include <cuda_runtime.h>
#include <cuda_bf16.h>
#include <cstdint>

#define D_MODEL 1024
#define SEQ     2048
#define NHEAD   16
#define NELEM   (8192 * 1024)

// ---------------- scratch (device globals) ----------------
__device__ __nv_bfloat16 g_xh[NELEM], g_xl[NELEM];
__device__ __nv_bfloat16 g_wth[4 * D_MODEL * D_MODEL], g_wtl[4 * D_MODEL * D_MODEL]; // W^T [n][k]
__device__ __nv_bfloat16 g_qh[NELEM], g_ql[NELEM];   // [bh][t][64], pre-scaled 1/8
__device__ __nv_bfloat16 g_kh[NELEM], g_kl[NELEM];   // [bh][t][64]
__device__ __nv_bfloat16 g_vh[NELEM], g_vl[NELEM];   // [bh][t][64]
__device__ __nv_bfloat16 g_ch[NELEM], g_cl[NELEM];   // ctx [m][1024]

// ---------------- helpers ----------------
__device__ __forceinline__ uint32_t smem_u32(const void* p) {
    uint32_t a;
    asm("{ .reg .u64 t; cvta.to.shared.u64 t, %1; cvt.u32.u64 %0, t; }" : "=r"(a) : "l"(p));
    return a;
}
__device__ __forceinline__ void mma16816(float* d, const uint32_t* a, const uint32_t* b) {
    asm volatile("mma.sync.aligned.m16n8k16.row.col.f32.bf16.bf16.f32 "
                 "{%0,%1,%2,%3}, {%4,%5,%6,%7}, {%8,%9}, {%0,%1,%2,%3};"
                 : "+f"(d[0]), "+f"(d[1]), "+f"(d[2]), "+f"(d[3])
                 : "r"(a[0]), "r"(a[1]), "r"(a[2]), "r"(a[3]), "r"(b[0]), "r"(b[1]));
}
__device__ __forceinline__ void ldm4(uint32_t* r, uint32_t a) {
    asm volatile("ldmatrix.sync.aligned.m8n8.x4.shared.b16 {%0,%1,%2,%3}, [%4];"
                 : "=r"(r[0]), "=r"(r[1]), "=r"(r[2]), "=r"(r[3]) : "r"(a));
}
__device__ __forceinline__ void ldm4t(uint32_t* r, uint32_t a) {
    asm volatile("ldmatrix.sync.aligned.m8n8.x4.trans.shared.b16 {%0,%1,%2,%3}, [%4];"
                 : "=r"(r[0]), "=r"(r[1]), "=r"(r[2]), "=r"(r[3]) : "r"(a));
}
#define CP16(s, g)  asm volatile("cp.async.cg.shared.global [%0], [%1], 16;" :: "r"(s), "l"(g))
#define CP_COMMIT() asm volatile("cp.async.commit_group;" ::: "memory")
#define CP_WAIT(n)  asm volatile("cp.async.wait_group %0;" :: "n"(n) : "memory")

__device__ __forceinline__ void split2(float v0, float v1, uint32_t& h, uint32_t& l) {
    __nv_bfloat16 h0 = __float2bfloat16(v0), h1 = __float2bfloat16(v1);
    h = ((uint32_t)__bfloat16_as_ushort(h1) << 16) | __bfloat16_as_ushort(h0);
    __nv_bfloat16 l0 = __float2bfloat16(v0 - __bfloat162float(h0));
    __nv_bfloat16 l1 = __float2bfloat16(v1 - __bfloat162float(h1));
    l = ((uint32_t)__bfloat16_as_ushort(l1) << 16) | __bfloat16_as_ushort(l0);
}

// ---------------- conversion kernels ----------------
__global__ void conv_split(const float* __restrict__ in, __nv_bfloat16* __restrict__ oh,
                           __nv_bfloat16* __restrict__ ol, int n) {
    for (int i = blockIdx.x * blockDim.x + threadIdx.x; i < n; i += gridDim.x * blockDim.x) {
        float v = in[i];
        __nv_bfloat16 h = __float2bfloat16(v);
        oh[i] = h;
        ol[i] = __float2bfloat16(v - __bfloat162float(h));
    }
}
__global__ void conv_wt(const float* W0, const float* W1, const float* W2, const float* W3,
                        __nv_bfloat16* __restrict__ oh, __nv_bfloat16* __restrict__ ol) {
    __shared__ float t[32][33];
    const float* W = (blockIdx.z == 0) ? W0 : (blockIdx.z == 1) ? W1 : (blockIdx.z == 2) ? W2 : W3;
    const size_t obase = (size_t)blockIdx.z * D_MODEL * D_MODEL;
    const int n0 = blockIdx.x * 32, k0 = blockIdx.y * 32;
    const int x = threadIdx.x, y = threadIdx.y;
    for (int i = 0; i < 32; i += 8)
        t[y + i][x] = W[(size_t)(k0 + y + i) * D_MODEL + n0 + x];
    __syncthreads();
    for (int i = 0; i < 32; i += 8) {
        float v = t[x][y + i];
        __nv_bfloat16 h = __float2bfloat16(v);
        const size_t o = obase + (size_t)(n0 + y + i) * D_MODEL + k0 + x;
        oh[o] = h;
        ol[o] = __float2bfloat16(v - __bfloat162float(h));
    }
}

// ---------------- projection GEMM (byte-identical to measured R10) ----------------
#define PSTR 40
#define PJ_ARR   (128 * PSTR)
#define PJ_STAGE (4 * PJ_ARR)
#define PJ_SMEM  (2 * PJ_STAGE * 2)      // 81920 bytes
__global__ void __launch_bounds__(256, 2)
proj_mma(const __nv_bfloat16* __restrict__ Ah, const __nv_bfloat16* __restrict__ Al,
         const __nv_bfloat16* __restrict__ Bh, const __nv_bfloat16* __restrict__ Bl,
         const float* __restrict__ bias, float scale, int mode,
         float* __restrict__ out32, __nv_bfloat16* __restrict__ oh, __nv_bfloat16* __restrict__ ol)
{
    extern __shared__ __nv_bfloat16 smp[];
    const uint32_t sbase = smem_u32(smp);

    const int tid = threadIdx.x, w = tid >> 5, lane = tid & 31;
    const int wm = w >> 2, wn = w & 3;
    const int m0 = blockIdx.y * 128, n0 = blockIdx.x * 128;
    const int lr = tid >> 2, lc = (tid & 3) * 8;
    const int qr = lane >> 2, qc = 2 * (lane & 3);
    const int arow = (lane & 7) + ((lane >> 3) & 1) * 8;
    const int acol = (lane >> 4) * 8;
    const int brow = (lane & 7) + ((lane >> 4) & 1) * 8;
    const int bcol = ((lane >> 3) & 1) * 8;

    float acc[4][4][4];
#pragma unroll
    for (int i = 0; i < 4; i++)
#pragma unroll
        for (int j = 0; j < 4; j++)
#pragma unroll
            for (int e = 0; e < 4; e++) acc[i][j][e] = 0.f;

#define PJ_ISSUE(kt, buf) do {                                                  \
    const uint32_t s0_ = sbase + (buf) * (PJ_STAGE * 2);                        \
    _Pragma("unroll")                                                           \
    for (int p_ = 0; p_ < 2; p_++) {                                            \
        const int r_ = lr + p_ * 64;                                            \
        const size_t ga_ = (size_t)(m0 + r_) * D_MODEL + (kt) * 32 + lc;        \
        const size_t gb_ = (size_t)(n0 + r_) * D_MODEL + (kt) * 32 + lc;        \
        const uint32_t so_ = (uint32_t)(r_ * PSTR + lc) * 2;                    \
        CP16(s0_ + so_,                 Ah + ga_);                              \
        CP16(s0_ + PJ_ARR * 2 + so_,    Al + ga_);                              \
        CP16(s0_ + PJ_ARR * 4 + so_,    Bh + gb_);                              \
        CP16(s0_ + PJ_ARR * 6 + so_,    Bl + gb_);                              \
    }                                                                           \
    CP_COMMIT(); } while (0)

    PJ_ISSUE(0, 0);
    for (int kt = 0; kt < 32; kt++) {
        if (kt + 1 < 32) { PJ_ISSUE(kt + 1, (kt + 1) & 1); CP_WAIT(1); }
        else             { CP_WAIT(0); }
        __syncthreads();

        const uint32_t s0 = sbase + (kt & 1) * (PJ_STAGE * 2);
        const uint32_t sAh = s0, sAl = s0 + PJ_ARR * 2,
                       sBh = s0 + PJ_ARR * 4, sBl = s0 + PJ_ARR * 6;
#pragma unroll
        for (int s = 0; s < 2; s++) {
            const int k0 = s * 16;
            uint32_t ah[4][4], al[4][4];
#pragma unroll
            for (int i = 0; i < 4; i++) {
                const int r = wm * 64 + i * 16 + arow;
                const uint32_t off = (uint32_t)(r * PSTR + k0 + acol) * 2;
                ldm4(ah[i], sAh + off);
                ldm4(al[i], sAl + off);
            }
#pragma unroll
            for (int jp = 0; jp < 2; jp++) {
                const int nA = wn * 32 + jp * 16 + brow;
                const uint32_t off = (uint32_t)(nA * PSTR + k0 + bcol) * 2;
                uint32_t bh4[4], bl4[4];
                ldm4(bh4, sBh + off);
                ldm4(bl4, sBl + off);
#pragma unroll
                for (int jj = 0; jj < 2; jj++)
#pragma unroll
                    for (int i = 0; i < 4; i++)
                        mma16816(acc[i][jp * 2 + jj], ah[i], bh4 + jj * 2);
#pragma unroll
                for (int jj = 0; jj < 2; jj++)
#pragma unroll
                    for (int i = 0; i < 4; i++)
                        mma16816(acc[i][jp * 2 + jj], ah[i], bl4 + jj * 2);
#pragma unroll
                for (int jj = 0; jj < 2; jj++)
#pragma unroll
                    for (int i = 0; i < 4; i++)
                        mma16816(acc[i][jp * 2 + jj], al[i], bh4 + jj * 2);
            }
        }
        __syncthreads();
    }

    // epilogue
#pragma unroll
    for (int j = 0; j < 4; j++) {
        const int c0 = n0 + wn * 32 + j * 8 + qc;
        const float b0 = bias[c0], b1 = bias[c0 + 1];
#pragma unroll
        for (int i = 0; i < 4; i++) {
            const int r0 = m0 + wm * 64 + i * 16 + qr;
            const float v00 = acc[i][j][0] + b0, v01 = acc[i][j][1] + b1;
            const float v10 = acc[i][j][2] + b0, v11 = acc[i][j][3] + b1;
            if (mode == 0) {
                *(float2*)(out32 + (size_t)r0 * D_MODEL + c0)       = make_float2(v00, v01);
                *(float2*)(out32 + (size_t)(r0 + 8) * D_MODEL + c0) = make_float2(v10, v11);
            } else {
                const int h = c0 >> 6, d = c0 & 63;
#pragma unroll
                for (int rr = 0; rr < 2; rr++) {
                    const int r = r0 + rr * 8;
                    const int b = r >> 11, t = r & 2047;
                    const float s0 = (rr ? v10 : v00) * scale, s1 = (rr ? v11 : v01) * scale;
                    uint32_t ph, pl;
                    split2(s0, s1, ph, pl);
                    const size_t idx = (((size_t)(b * NHEAD + h)) * SEQ + t) * 64 + d;
                    *(uint32_t*)(oh + idx) = ph;
                    *(uint32_t*)(ol + idx) = pl;
                }
            }
        }
    }
}

// ---------------- attention: FULL 3-term math + 3-stage single-barrier pipeline ----
#define ASTR 72
#define AT_ARR   (64 * ASTR)
#define AT_STAGE (4 * AT_ARR)            // Kh, Kl, Vh, Vl
#define AT_SMEM  (3 * AT_STAGE * 2)      // 110592 bytes; x2 CTAs = 221184 <= 227KB
__global__ void __launch_bounds__(256, 2)
attn_mma(const __nv_bfloat16* __restrict__ qh, const __nv_bfloat16* __restrict__ ql,
         const __nv_bfloat16* __restrict__ kh, const __nv_bfloat16* __restrict__ kl,
         const __nv_bfloat16* __restrict__ vh, const __nv_bfloat16* __restrict__ vl,
         const int* __restrict__ mask,
         __nv_bfloat16* __restrict__ ch, __nv_bfloat16* __restrict__ cl)
{
    extern __shared__ __nv_bfloat16 smp[];
    __shared__ int smask[3][64];
    const uint32_t sbase = smem_u32(smp);

    const int tid = threadIdx.x, w = tid >> 5, lane = tid & 31;
    const int qr4 = lane >> 2, qc = 2 * (lane & 3);
    const int bh = blockIdx.y, b = bh >> 4, hh = bh & 15;
    const int q0 = blockIdx.x * 128;
    const int qrow = q0 + w * 16 + qr4;
    const int brow = (lane & 7) + ((lane >> 4) & 1) * 8;
    const int bcol = ((lane >> 3) & 1) * 8;

    // Q fragments (persistent): 4 k16 tiles over d=64, hi/lo
    uint32_t qfh[4][4], qfl[4][4];
    {
        const size_t qb = ((size_t)bh * SEQ + qrow) * 64;
#pragma unroll
        for (int s = 0; s < 4; s++) {
            const __nv_bfloat16* p = qh + qb + s * 16 + qc;
            qfh[s][0] = *(const uint32_t*)p;
            qfh[s][1] = *(const uint32_t*)(p + 8 * 64);
            qfh[s][2] = *(const uint32_t*)(p + 8);
            qfh[s][3] = *(const uint32_t*)(p + 8 * 64 + 8);
            const __nv_bfloat16* pl = ql + qb + s * 16 + qc;
            qfl[s][0] = *(const uint32_t*)pl;
            qfl[s][1] = *(const uint32_t*)(pl + 8 * 64);
            qfl[s][2] = *(const uint32_t*)(pl + 8);
            qfl[s][3] = *(const uint32_t*)(pl + 8 * 64 + 8);
        }
    }

    float oacc[8][4];
#pragma unroll
    for (int j = 0; j < 8; j++)
#pragma unroll
        for (int e = 0; e < 4; e++) oacc[j][e] = 0.f;
    float lsum0 = 0.f, lsum1 = 0.f;

#define AT_ISSUE(kt, buf) do {                                                  \
    const uint32_t s0_ = sbase + (buf) * (AT_STAGE * 2);                        \
    _Pragma("unroll")                                                           \
    for (int p_ = 0; p_ < 2; p_++) {                                            \
        const int r_ = (tid >> 3) + p_ * 32;                                    \
        const int c_ = (tid & 7) * 8;                                           \
        const size_t g_ = ((size_t)bh * SEQ + (kt) * 64 + r_) * 64 + c_;        \
        const uint32_t so_ = (uint32_t)(r_ * ASTR + c_) * 2;                    \
        CP16(s0_ + so_,               kh + g_);                                 \
        CP16(s0_ + AT_ARR * 2 + so_,  kl + g_);                                 \
        CP16(s0_ + AT_ARR * 4 + so_,  vh + g_);                                 \
        CP16(s0_ + AT_ARR * 6 + so_,  vl + g_);                                 \
    }                                                                           \
    if (tid < 64) smask[buf][tid] = mask[b * SEQ + (kt) * 64 + tid];            \
    CP_COMMIT(); } while (0)

    AT_ISSUE(0, 0);
    AT_ISSUE(1, 1);
    int buf2 = 2;   // buffer slot for the next issue (kt+2)
    for (int kt = 0; kt < 32; kt++) {
        if (kt == 31) CP_WAIT(0); else CP_WAIT(1);
        __syncthreads();
        if (kt + 2 < 32) {
            AT_ISSUE(kt + 2, buf2);
        }
        const int cur = (buf2 + 1 == 3) ? 0 : buf2 + 1;
        buf2 = cur;

        const uint32_t s0 = sbase + (uint32_t)(kt % 3) * (AT_STAGE * 2);
        const uint32_t sKh = s0, sKl = s0 + AT_ARR * 2,
                       sVh = s0 + AT_ARR * 4, sVl = s0 + AT_ARR * 6;
        const int* mk = smask[kt % 3];

        // S = Qh*Kh + Qh*Kl + Ql*Kh  (3 terms)
        float s4[8][4];
#pragma unroll
        for (int j = 0; j < 8; j++)
#pragma unroll
            for (int e = 0; e < 4; e++) s4[j][e] = 0.f;
#pragma unroll
        for (int jp = 0; jp < 4; jp++) {
            const int nA = jp * 16 + brow;
#pragma unroll
            for (int s = 0; s < 4; s++) {
                const uint32_t off = (uint32_t)(nA * ASTR + s * 16 + bcol) * 2;
                uint32_t bh4[4], bl4[4];
                ldm4(bh4, sKh + off);
                ldm4(bl4, sKl + off);
#pragma unroll
                for (int jj = 0; jj < 2; jj++)
                    mma16816(s4[jp * 2 + jj], qfh[s], bh4 + jj * 2);
#pragma unroll
                for (int jj = 0; jj < 2; jj++)
                    mma16816(s4[jp * 2 + jj], qfh[s], bl4 + jj * 2);
#pragma unroll
                for (int jj = 0; jj < 2; jj++)
                    mma16816(s4[jp * 2 + jj], qfl[s], bh4 + jj * 2);
            }
        }

        // softmax (no max) + hi/lo repack into P A-frags
        uint32_t pfh[4][4], pfl[4][4];
#pragma unroll
        for (int j = 0; j < 8; j++) {
            const int c0 = j * 8 + qc;
            const int m0v = mk[c0], m1v = mk[c0 + 1];
            const float e0 = m0v ? __expf(fminf(s4[j][0], 60.f)) : 0.f;
            const float e1 = m1v ? __expf(fminf(s4[j][1], 60.f)) : 0.f;
            const float e2 = m0v ? __expf(fminf(s4[j][2], 60.f)) : 0.f;
            const float e3 = m1v ? __expf(fminf(s4[j][3], 60.f)) : 0.f;
            lsum0 += e0 + e1;
            lsum1 += e2 + e3;
            uint32_t h01, l01, h23, l23;
            split2(e0, e1, h01, l01);
            split2(e2, e3, h23, l23);
            const int t = j >> 1, o = (j & 1) * 2;
            pfh[t][o] = h01; pfh[t][o + 1] = h23;
            pfl[t][o] = l01; pfl[t][o + 1] = l23;
        }

        // O += Ph*Vh + Ph*Vl + Pl*Vh  (3 terms; V transposed by ldmatrix.trans)
#pragma unroll
        for (int jd = 0; jd < 8; jd++) {
#pragma unroll
            for (int tp = 0; tp < 2; tp++) {
                const uint32_t off = (uint32_t)((tp * 32 + lane) * ASTR + jd * 8) * 2;
                uint32_t v4h[4], v4l[4];
                ldm4t(v4h, sVh + off);
                ldm4t(v4l, sVl + off);
                mma16816(oacc[jd], pfh[tp * 2],     v4h);
                mma16816(oacc[jd], pfh[tp * 2 + 1], v4h + 2);
                mma16816(oacc[jd], pfh[tp * 2],     v4l);
                mma16816(oacc[jd], pfh[tp * 2 + 1], v4l + 2);
                mma16816(oacc[jd], pfl[tp * 2],     v4h);
                mma16816(oacc[jd], pfl[tp * 2 + 1], v4h + 2);
            }
        }
    }

    // quad row-sum reduction
    lsum0 += __shfl_xor_sync(0xffffffffu, lsum0, 1);
    lsum0 += __shfl_xor_sync(0xffffffffu, lsum0, 2);
    lsum1 += __shfl_xor_sync(0xffffffffu, lsum1, 1);
    lsum1 += __shfl_xor_sync(0xffffffffu, lsum1, 2);
    const float inv0 = 1.f / lsum0, inv1 = 1.f / lsum1;

    const size_t base0 = ((size_t)b * SEQ + qrow) * D_MODEL + hh * 64;
    const size_t base1 = base0 + 8 * D_MODEL;
#pragma unroll
    for (int jd = 0; jd < 8; jd++) {
        const int d0 = jd * 8 + qc;
        uint32_t ph, pl;
        split2(oacc[jd][0] * inv0, oacc[jd][1] * inv0, ph, pl);
        *(uint32_t*)(ch + base0 + d0) = ph;
        *(uint32_t*)(cl + base0 + d0) = pl;
        split2(oacc[jd][2] * inv1, oacc[jd][3] * inv1, ph, pl);
        *(uint32_t*)(ch + base1 + d0) = ph;
        *(uint32_t*)(cl + base1 + d0) = pl;
    }
}

// ---------------- kernel_launch ----------------
extern "C" void kernel_launch(void* const* d_in, const int* in_sizes, int n_in,
                              void* d_out, int out_size)
{
    const float* x    = (const float*)d_in[0];
    const int*   mask = (const int*)  d_in[1];
    const float* Wq   = (const float*)d_in[2];
    const float* bq   = (const float*)d_in[3];
    const float* Wk   = (const float*)d_in[4];
    const float* bk   = (const float*)d_in[5];
    const float* Wv   = (const float*)d_in[6];
    const float* bv   = (const float*)d_in[7];
    const float* Wo   = (const float*)d_in[8];
    const float* bo   = (const float*)d_in[9];
    float* out = (float*)d_out;

    __nv_bfloat16 *xh, *xl, *wth, *wtl, *qh, *ql, *kh, *kl, *vh, *vl, *chp, *clp;
    cudaGetSymbolAddress((void**)&xh,  g_xh);
    cudaGetSymbolAddress((void**)&xl,  g_xl);
    cudaGetSymbolAddress((void**)&wth, g_wth);
    cudaGetSymbolAddress((void**)&wtl, g_wtl);
    cudaGetSymbolAddress((void**)&qh,  g_qh);
    cudaGetSymbolAddress((void**)&ql,  g_ql);
    cudaGetSymbolAddress((void**)&kh,  g_kh);
    cudaGetSymbolAddress((void**)&kl,  g_kl);
    cudaGetSymbolAddress((void**)&vh,  g_vh);
    cudaGetSymbolAddress((void**)&vl,  g_vl);
    cudaGetSymbolAddress((void**)&chp, g_ch);
    cudaGetSymbolAddress((void**)&clp, g_cl);

    cudaFuncSetAttribute(proj_mma, cudaFuncAttributeMaxDynamicSharedMemorySize, PJ_SMEM);
    cudaFuncSetAttribute(attn_mma, cudaFuncAttributeMaxDynamicSharedMemorySize, AT_SMEM);

    conv_split<<<4096, 256>>>(x, xh, xl, NELEM);
    conv_wt<<<dim3(32, 32, 4), dim3(32, 8)>>>(Wq, Wk, Wv, Wo, wth, wtl);

    const size_t WSZ = (size_t)D_MODEL * D_MODEL;
    dim3 pg(8, 64);
    proj_mma<<<pg, 256, PJ_SMEM>>>(xh, xl, wth + 0 * WSZ, wtl + 0 * WSZ, bq, 0.125f, 1, nullptr, qh, ql);
    proj_mma<<<pg, 256, PJ_SMEM>>>(xh, xl, wth + 1 * WSZ, wtl + 1 * WSZ, bk, 1.f,    1, nullptr, kh, kl);
    proj_mma<<<pg, 256, PJ_SMEM>>>(xh, xl, wth + 2 * WSZ, wtl + 2 * WSZ, bv, 1.f,    1, nullptr, vh, vl);

    attn_mma<<<dim3(16, 64), 256, AT_SMEM>>>(qh, ql, kh, kl, vh, vl, mask, chp, clp);

    proj_mma<<<pg, 256, PJ_SMEM>>>(chp, clp, wth + 3 * WSZ, wtl + 3 * WSZ, bo, 1.f, 0, out, nullptr, nullptr);
}

// round 16
// speedup vs baseline: 1.0092x; 1.0092x over previous
#include <cuda_runtime.h>
#include <cuda_bf16.h>
#include <cstdint>

#define D_MODEL 1024
#define SEQ     2048
#define NHEAD   16
#define NELEM   (8192 * 1024)

// ---------------- scratch (device globals) ----------------
__device__ __nv_bfloat16 g_xh[NELEM], g_xl[NELEM];
__device__ __nv_bfloat16 g_wth[4 * D_MODEL * D_MODEL], g_wtl[4 * D_MODEL * D_MODEL]; // W^T [n][k]
__device__ __nv_bfloat16 g_qh[NELEM], g_ql[NELEM];   // [bh][t][64], pre-scaled 1/8
__device__ __nv_bfloat16 g_kh[NELEM], g_kl[NELEM];   // [bh][t][64]
__device__ __nv_bfloat16 g_vh[NELEM], g_vl[NELEM];   // [bh][t][64]
__device__ __nv_bfloat16 g_ch[NELEM], g_cl[NELEM];   // ctx [m][1024]

// ---------------- helpers ----------------
__device__ __forceinline__ uint32_t smem_u32(const void* p) {
    uint32_t a;
    asm("{ .reg .u64 t; cvta.to.shared.u64 t, %1; cvt.u32.u64 %0, t; }" : "=r"(a) : "l"(p));
    return a;
}
__device__ __forceinline__ void mma16816(float* d, const uint32_t* a, const uint32_t* b) {
    asm volatile("mma.sync.aligned.m16n8k16.row.col.f32.bf16.bf16.f32 "
                 "{%0,%1,%2,%3}, {%4,%5,%6,%7}, {%8,%9}, {%0,%1,%2,%3};"
                 : "+f"(d[0]), "+f"(d[1]), "+f"(d[2]), "+f"(d[3])
                 : "r"(a[0]), "r"(a[1]), "r"(a[2]), "r"(a[3]), "r"(b[0]), "r"(b[1]));
}
__device__ __forceinline__ void ldm4(uint32_t* r, uint32_t a) {
    asm volatile("ldmatrix.sync.aligned.m8n8.x4.shared.b16 {%0,%1,%2,%3}, [%4];"
                 : "=r"(r[0]), "=r"(r[1]), "=r"(r[2]), "=r"(r[3]) : "r"(a));
}
__device__ __forceinline__ void ldm4t(uint32_t* r, uint32_t a) {
    asm volatile("ldmatrix.sync.aligned.m8n8.x4.trans.shared.b16 {%0,%1,%2,%3}, [%4];"
                 : "=r"(r[0]), "=r"(r[1]), "=r"(r[2]), "=r"(r[3]) : "r"(a));
}
#define CP16(s, g)  asm volatile("cp.async.cg.shared.global [%0], [%1], 16;" :: "r"(s), "l"(g))
#define CP_COMMIT() asm volatile("cp.async.commit_group;" ::: "memory")
#define CP_WAIT(n)  asm volatile("cp.async.wait_group %0;" :: "n"(n) : "memory")

__device__ __forceinline__ void split2(float v0, float v1, uint32_t& h, uint32_t& l) {
    __nv_bfloat16 h0 = __float2bfloat16(v0), h1 = __float2bfloat16(v1);
    h = ((uint32_t)__bfloat16_as_ushort(h1) << 16) | __bfloat16_as_ushort(h0);
    __nv_bfloat16 l0 = __float2bfloat16(v0 - __bfloat162float(h0));
    __nv_bfloat16 l1 = __float2bfloat16(v1 - __bfloat162float(h1));
    l = ((uint32_t)__bfloat16_as_ushort(l1) << 16) | __bfloat16_as_ushort(l0);
}

// ---------------- conversion kernels ----------------
__global__ void conv_split(const float* __restrict__ in, __nv_bfloat16* __restrict__ oh,
                           __nv_bfloat16* __restrict__ ol, int n) {
    for (int i = blockIdx.x * blockDim.x + threadIdx.x; i < n; i += gridDim.x * blockDim.x) {
        float v = in[i];
        __nv_bfloat16 h = __float2bfloat16(v);
        oh[i] = h;
        ol[i] = __float2bfloat16(v - __bfloat162float(h));
    }
}
__global__ void conv_wt(const float* W0, const float* W1, const float* W2, const float* W3,
                        __nv_bfloat16* __restrict__ oh, __nv_bfloat16* __restrict__ ol) {
    __shared__ float t[32][33];
    const float* W = (blockIdx.z == 0) ? W0 : (blockIdx.z == 1) ? W1 : (blockIdx.z == 2) ? W2 : W3;
    const size_t obase = (size_t)blockIdx.z * D_MODEL * D_MODEL;
    const int n0 = blockIdx.x * 32, k0 = blockIdx.y * 32;
    const int x = threadIdx.x, y = threadIdx.y;
    for (int i = 0; i < 32; i += 8)
        t[y + i][x] = W[(size_t)(k0 + y + i) * D_MODEL + n0 + x];
    __syncthreads();
    for (int i = 0; i < 32; i += 8) {
        float v = t[x][y + i];
        __nv_bfloat16 h = __float2bfloat16(v);
        const size_t o = obase + (size_t)(n0 + y + i) * D_MODEL + k0 + x;
        oh[o] = h;
        ol[o] = __float2bfloat16(v - __bfloat162float(h));
    }
}

// ---------------- projection GEMM v2: 128x64 tile, occupancy 3 ----------------
// 8 warps as 2(m)x4(n); warp tile 64x16 (mtiles 4 x ntiles 2). K chunks of 32, 2 stages.
#define PSTR 40
#define PJ_A_ARR (128 * PSTR)            // 5120 elems
#define PJ_B_ARR (64 * PSTR)             // 2560 elems
#define PJ_STAGE (2 * PJ_A_ARR + 2 * PJ_B_ARR)   // 15360 elems
#define PJ_SMEM  (2 * PJ_STAGE * 2)      // 61440 bytes; x3 CTAs = 184KB
__global__ void __launch_bounds__(256, 3)
proj_mma(const __nv_bfloat16* __restrict__ Ah, const __nv_bfloat16* __restrict__ Al,
         const __nv_bfloat16* __restrict__ Bh, const __nv_bfloat16* __restrict__ Bl,
         const float* __restrict__ bias, float scale, int mode,
         float* __restrict__ out32, __nv_bfloat16* __restrict__ oh, __nv_bfloat16* __restrict__ ol)
{
    extern __shared__ __nv_bfloat16 smp[];
    const uint32_t sbase = smem_u32(smp);

    const int tid = threadIdx.x, w = tid >> 5, lane = tid & 31;
    const int wm = w >> 2, wn = w & 3;           // 2 m-groups of 64, 4 n-groups of 16
    const int m0 = blockIdx.y * 128, n0 = blockIdx.x * 64;
    const int lr = tid >> 2, lc = (tid & 3) * 8;
    const int qr = lane >> 2, qc = 2 * (lane & 3);
    const int arow = (lane & 7) + ((lane >> 3) & 1) * 8;
    const int acol = (lane >> 4) * 8;
    const int brow = (lane & 7) + ((lane >> 4) & 1) * 8;
    const int bcol = ((lane >> 3) & 1) * 8;

    float acc[4][2][4];
#pragma unroll
    for (int i = 0; i < 4; i++)
#pragma unroll
        for (int j = 0; j < 2; j++)
#pragma unroll
            for (int e = 0; e < 4; e++) acc[i][j][e] = 0.f;

#define PJ_ISSUE(kt, buf) do {                                                  \
    const uint32_t s0_ = sbase + (buf) * (PJ_STAGE * 2);                        \
    _Pragma("unroll")                                                           \
    for (int p_ = 0; p_ < 2; p_++) {                                            \
        const int r_ = lr + p_ * 64;                                            \
        const size_t ga_ = (size_t)(m0 + r_) * D_MODEL + (kt) * 32 + lc;        \
        const uint32_t so_ = (uint32_t)(r_ * PSTR + lc) * 2;                    \
        CP16(s0_ + so_,                  Ah + ga_);                             \
        CP16(s0_ + PJ_A_ARR * 2 + so_,   Al + ga_);                             \
    }                                                                           \
    {                                                                           \
        const int r_ = lr;                                                      \
        const size_t gb_ = (size_t)(n0 + r_) * D_MODEL + (kt) * 32 + lc;        \
        const uint32_t so_ = (uint32_t)(r_ * PSTR + lc) * 2;                    \
        CP16(s0_ + PJ_A_ARR * 4 + so_,                  Bh + gb_);              \
        CP16(s0_ + PJ_A_ARR * 4 + PJ_B_ARR * 2 + so_,   Bl + gb_);              \
    }                                                                           \
    CP_COMMIT(); } while (0)

    PJ_ISSUE(0, 0);
    for (int kt = 0; kt < 32; kt++) {
        if (kt + 1 < 32) { PJ_ISSUE(kt + 1, (kt + 1) & 1); CP_WAIT(1); }
        else             { CP_WAIT(0); }
        __syncthreads();

        const uint32_t s0 = sbase + (kt & 1) * (PJ_STAGE * 2);
        const uint32_t sAh = s0, sAl = s0 + PJ_A_ARR * 2,
                       sBh = s0 + PJ_A_ARR * 4, sBl = sBh + PJ_B_ARR * 2;
#pragma unroll
        for (int s = 0; s < 2; s++) {
            const int k0 = s * 16;
            // B fragments for this warp's 16 columns (one x4 pair)
            const int nA = wn * 16 + brow;
            const uint32_t boff = (uint32_t)(nA * PSTR + k0 + bcol) * 2;
            uint32_t bh4[4], bl4[4];
            ldm4(bh4, sBh + boff);
            ldm4(bl4, sBl + boff);
#pragma unroll
            for (int i = 0; i < 4; i++) {
                const int r = wm * 64 + i * 16 + arow;
                const uint32_t aoff = (uint32_t)(r * PSTR + k0 + acol) * 2;
                uint32_t ah[4], al[4];
                ldm4(ah, sAh + aoff);
                ldm4(al, sAl + aoff);
#pragma unroll
                for (int jj = 0; jj < 2; jj++) {
                    mma16816(acc[i][jj], ah, bh4 + jj * 2);
                    mma16816(acc[i][jj], ah, bl4 + jj * 2);
                    mma16816(acc[i][jj], al, bh4 + jj * 2);
                }
            }
        }
        __syncthreads();
    }

    // epilogue
#pragma unroll
    for (int j = 0; j < 2; j++) {
        const int c0 = n0 + wn * 16 + j * 8 + qc;
        const float b0 = bias[c0], b1 = bias[c0 + 1];
#pragma unroll
        for (int i = 0; i < 4; i++) {
            const int r0 = m0 + wm * 64 + i * 16 + qr;
            const float v00 = acc[i][j][0] + b0, v01 = acc[i][j][1] + b1;
            const float v10 = acc[i][j][2] + b0, v11 = acc[i][j][3] + b1;
            if (mode == 0) {
                *(float2*)(out32 + (size_t)r0 * D_MODEL + c0)       = make_float2(v00, v01);
                *(float2*)(out32 + (size_t)(r0 + 8) * D_MODEL + c0) = make_float2(v10, v11);
            } else {
                const int h = c0 >> 6, d = c0 & 63;
#pragma unroll
                for (int rr = 0; rr < 2; rr++) {
                    const int r = r0 + rr * 8;
                    const int b = r >> 11, t = r & 2047;
                    const float s0 = (rr ? v10 : v00) * scale, s1 = (rr ? v11 : v01) * scale;
                    uint32_t ph, pl;
                    split2(s0, s1, ph, pl);
                    const size_t idx = (((size_t)(b * NHEAD + h)) * SEQ + t) * 64 + d;
                    *(uint32_t*)(oh + idx) = ph;
                    *(uint32_t*)(ol + idx) = pl;
                }
            }
        }
    }
}

// ---------------- attention (byte-exact R10 measured-best version) ----------------
#define ASTR 72
#define AT_ARR   (64 * ASTR)
#define AT_STAGE (4 * AT_ARR)
#define AT_SMEM  (2 * AT_STAGE * 2)      // 73728 bytes; x2 CTAs = 144KB
__global__ void __launch_bounds__(256, 2)
attn_mma(const __nv_bfloat16* __restrict__ qh, const __nv_bfloat16* __restrict__ ql,
         const __nv_bfloat16* __restrict__ kh, const __nv_bfloat16* __restrict__ kl,
         const __nv_bfloat16* __restrict__ vh, const __nv_bfloat16* __restrict__ vl,
         const int* __restrict__ mask,
         __nv_bfloat16* __restrict__ ch, __nv_bfloat16* __restrict__ cl)
{
    extern __shared__ __nv_bfloat16 smp[];
    __shared__ int smask[2][64];
    const uint32_t sbase = smem_u32(smp);

    const int tid = threadIdx.x, w = tid >> 5, lane = tid & 31;
    const int qr4 = lane >> 2, qc = 2 * (lane & 3);
    const int bh = blockIdx.y, b = bh >> 4, hh = bh & 15;
    const int q0 = blockIdx.x * 128;
    const int qrow = q0 + w * 16 + qr4;
    const int brow = (lane & 7) + ((lane >> 4) & 1) * 8;
    const int bcol = ((lane >> 3) & 1) * 8;

    uint32_t qfh[4][4], qfl[4][4];
    {
        const size_t qb = ((size_t)bh * SEQ + qrow) * 64;
#pragma unroll
        for (int s = 0; s < 4; s++) {
            const __nv_bfloat16* p = qh + qb + s * 16 + qc;
            qfh[s][0] = *(const uint32_t*)p;
            qfh[s][1] = *(const uint32_t*)(p + 8 * 64);
            qfh[s][2] = *(const uint32_t*)(p + 8);
            qfh[s][3] = *(const uint32_t*)(p + 8 * 64 + 8);
            const __nv_bfloat16* pl = ql + qb + s * 16 + qc;
            qfl[s][0] = *(const uint32_t*)pl;
            qfl[s][1] = *(const uint32_t*)(pl + 8 * 64);
            qfl[s][2] = *(const uint32_t*)(pl + 8);
            qfl[s][3] = *(const uint32_t*)(pl + 8 * 64 + 8);
        }
    }

    float oacc[8][4];
#pragma unroll
    for (int j = 0; j < 8; j++)
#pragma unroll
        for (int e = 0; e < 4; e++) oacc[j][e] = 0.f;
    float lsum0 = 0.f, lsum1 = 0.f;

#define AT_ISSUE(kt, buf) do {                                                  \
    const uint32_t s0_ = sbase + (buf) * (AT_STAGE * 2);                        \
    _Pragma("unroll")                                                           \
    for (int p_ = 0; p_ < 2; p_++) {                                            \
        const int r_ = (tid >> 3) + p_ * 32;                                    \
        const int c_ = (tid & 7) * 8;                                           \
        const size_t g_ = ((size_t)bh * SEQ + (kt) * 64 + r_) * 64 + c_;        \
        const uint32_t so_ = (uint32_t)(r_ * ASTR + c_) * 2;                    \
        CP16(s0_ + so_,               kh + g_);                                 \
        CP16(s0_ + AT_ARR * 2 + so_,  kl + g_);                                 \
        CP16(s0_ + AT_ARR * 4 + so_,  vh + g_);                                 \
        CP16(s0_ + AT_ARR * 6 + so_,  vl + g_);                                 \
    }                                                                           \
    if (tid < 64) smask[buf][tid] = mask[b * SEQ + (kt) * 64 + tid];            \
    CP_COMMIT(); } while (0)

    AT_ISSUE(0, 0);
    for (int kt = 0; kt < 32; kt++) {
        if (kt + 1 < 32) { AT_ISSUE(kt + 1, (kt + 1) & 1); CP_WAIT(1); }
        else             { CP_WAIT(0); }
        __syncthreads();

        const uint32_t s0 = sbase + (kt & 1) * (AT_STAGE * 2);
        const uint32_t sKh = s0, sKl = s0 + AT_ARR * 2,
                       sVh = s0 + AT_ARR * 4, sVl = s0 + AT_ARR * 6;
        const int* mk = smask[kt & 1];

        // S = Qh*Kh + Qh*Kl + Ql*Kh
        float s4[8][4];
#pragma unroll
        for (int j = 0; j < 8; j++)
#pragma unroll
            for (int e = 0; e < 4; e++) s4[j][e] = 0.f;
#pragma unroll
        for (int jp = 0; jp < 4; jp++) {
            const int nA = jp * 16 + brow;
#pragma unroll
            for (int s = 0; s < 4; s++) {
                const uint32_t off = (uint32_t)(nA * ASTR + s * 16 + bcol) * 2;
                uint32_t bh4[4], bl4[4];
                ldm4(bh4, sKh + off);
                ldm4(bl4, sKl + off);
#pragma unroll
                for (int jj = 0; jj < 2; jj++)
                    mma16816(s4[jp * 2 + jj], qfh[s], bh4 + jj * 2);
#pragma unroll
                for (int jj = 0; jj < 2; jj++)
                    mma16816(s4[jp * 2 + jj], qfh[s], bl4 + jj * 2);
#pragma unroll
                for (int jj = 0; jj < 2; jj++)
                    mma16816(s4[jp * 2 + jj], qfl[s], bh4 + jj * 2);
            }
        }

        // softmax (no max) + hi/lo repack into P A-frags
        uint32_t pfh[4][4], pfl[4][4];
#pragma unroll
        for (int j = 0; j < 8; j++) {
            const int c0 = j * 8 + qc;
            const int m0v = mk[c0], m1v = mk[c0 + 1];
            const float e0 = m0v ? __expf(fminf(s4[j][0], 60.f)) : 0.f;
            const float e1 = m1v ? __expf(fminf(s4[j][1], 60.f)) : 0.f;
            const float e2 = m0v ? __expf(fminf(s4[j][2], 60.f)) : 0.f;
            const float e3 = m1v ? __expf(fminf(s4[j][3], 60.f)) : 0.f;
            lsum0 += e0 + e1;
            lsum1 += e2 + e3;
            uint32_t h01, l01, h23, l23;
            split2(e0, e1, h01, l01);
            split2(e2, e3, h23, l23);
            const int t = j >> 1, o = (j & 1) * 2;
            pfh[t][o] = h01; pfh[t][o + 1] = h23;
            pfl[t][o] = l01; pfl[t][o + 1] = l23;
        }

        // O += Ph*Vh + Ph*Vl + Pl*Vh
#pragma unroll
        for (int jd = 0; jd < 8; jd++) {
#pragma unroll
            for (int tp = 0; tp < 2; tp++) {
                const uint32_t off = (uint32_t)((tp * 32 + lane) * ASTR + jd * 8) * 2;
                uint32_t v4h[4], v4l[4];
                ldm4t(v4h, sVh + off);
                ldm4t(v4l, sVl + off);
                mma16816(oacc[jd], pfh[tp * 2],     v4h);
                mma16816(oacc[jd], pfh[tp * 2 + 1], v4h + 2);
                mma16816(oacc[jd], pfh[tp * 2],     v4l);
                mma16816(oacc[jd], pfh[tp * 2 + 1], v4l + 2);
                mma16816(oacc[jd], pfl[tp * 2],     v4h);
                mma16816(oacc[jd], pfl[tp * 2 + 1], v4h + 2);
            }
        }
        __syncthreads();
    }

    // quad row-sum reduction
    lsum0 += __shfl_xor_sync(0xffffffffu, lsum0, 1);
    lsum0 += __shfl_xor_sync(0xffffffffu, lsum0, 2);
    lsum1 += __shfl_xor_sync(0xffffffffu, lsum1, 1);
    lsum1 += __shfl_xor_sync(0xffffffffu, lsum1, 2);
    const float inv0 = 1.f / lsum0, inv1 = 1.f / lsum1;

    const size_t base0 = ((size_t)b * SEQ + qrow) * D_MODEL + hh * 64;
    const size_t base1 = base0 + 8 * D_MODEL;
#pragma unroll
    for (int jd = 0; jd < 8; jd++) {
        const int d0 = jd * 8 + qc;
        uint32_t ph, pl;
        split2(oacc[jd][0] * inv0, oacc[jd][1] * inv0, ph, pl);
        *(uint32_t*)(ch + base0 + d0) = ph;
        *(uint32_t*)(cl + base0 + d0) = pl;
        split2(oacc[jd][2] * inv1, oacc[jd][3] * inv1, ph, pl);
        *(uint32_t*)(ch + base1 + d0) = ph;
        *(uint32_t*)(cl + base1 + d0) = pl;
    }
}

// ---------------- kernel_launch ----------------
extern "C" void kernel_launch(void* const* d_in, const int* in_sizes, int n_in,
                              void* d_out, int out_size)
{
    const float* x    = (const float*)d_in[0];
    const int*   mask = (const int*)  d_in[1];
    const float* Wq   = (const float*)d_in[2];
    const float* bq   = (const float*)d_in[3];
    const float* Wk   = (const float*)d_in[4];
    const float* bk   = (const float*)d_in[5];
    const float* Wv   = (const float*)d_in[6];
    const float* bv   = (const float*)d_in[7];
    const float* Wo   = (const float*)d_in[8];
    const float* bo   = (const float*)d_in[9];
    float* out = (float*)d_out;

    __nv_bfloat16 *xh, *xl, *wth, *wtl, *qh, *ql, *kh, *kl, *vh, *vl, *chp, *clp;
    cudaGetSymbolAddress((void**)&xh,  g_xh);
    cudaGetSymbolAddress((void**)&xl,  g_xl);
    cudaGetSymbolAddress((void**)&wth, g_wth);
    cudaGetSymbolAddress((void**)&wtl, g_wtl);
    cudaGetSymbolAddress((void**)&qh,  g_qh);
    cudaGetSymbolAddress((void**)&ql,  g_ql);
    cudaGetSymbolAddress((void**)&kh,  g_kh);
    cudaGetSymbolAddress((void**)&kl,  g_kl);
    cudaGetSymbolAddress((void**)&vh,  g_vh);
    cudaGetSymbolAddress((void**)&vl,  g_vl);
    cudaGetSymbolAddress((void**)&chp, g_ch);
    cudaGetSymbolAddress((void**)&clp, g_cl);

    cudaFuncSetAttribute(proj_mma, cudaFuncAttributeMaxDynamicSharedMemorySize, PJ_SMEM);
    cudaFuncSetAttribute(attn_mma, cudaFuncAttributeMaxDynamicSharedMemorySize, AT_SMEM);

    conv_split<<<4096, 256>>>(x, xh, xl, NELEM);
    conv_wt<<<dim3(32, 32, 4), dim3(32, 8)>>>(Wq, Wk, Wv, Wo, wth, wtl);

    const size_t WSZ = (size_t)D_MODEL * D_MODEL;
    dim3 pg(16, 64);   // 128x64 tiles
    proj_mma<<<pg, 256, PJ_SMEM>>>(xh, xl, wth + 0 * WSZ, wtl + 0 * WSZ, bq, 0.125f, 1, nullptr, qh, ql);
    proj_mma<<<pg, 256, PJ_SMEM>>>(xh, xl, wth + 1 * WSZ, wtl + 1 * WSZ, bk, 1.f,    1, nullptr, kh, kl);
    proj_mma<<<pg, 256, PJ_SMEM>>>(xh, xl, wth + 2 * WSZ, wtl + 2 * WSZ, bv, 1.f,    1, nullptr, vh, vl);

    attn_mma<<<dim3(16, 64), 256, AT_SMEM>>>(qh, ql, kh, kl, vh, vl, mask, chp, clp);

    proj_mma<<<pg, 256, PJ_SMEM>>>(chp, clp, wth + 3 * WSZ, wtl + 3 * WSZ, bo, 1.f, 0, out, nullptr, nullptr);
}